// round 13
// baseline (speedup 1.0000x reference)
#include <cuda_runtime.h>
#include <cuda_bf16.h>
#include <cstdint>

// Problem constants
#define CC 8
#define KK 64
#define DD 32
#define NN 2048

// Packed per-(c,k) weight block layout (floats)
#define PK      4352
#define NETOFF  2128
#define O_W1S   0      // [64][16]
#define O_B1S   1024   // [64]
#define O_W2S   1088   // [64][16]  transposed: [j][i] = W2[ud(i)][j]
#define O_B2S   2112   // [16]
#define O_W1T   2128
#define O_B1T   3152
#define O_W2T   3216
#define O_B2T   4240
#define O_ANE   4256   // [parity][16] exp(-an_s), parity-pair-packed
#define O_ANB   4288   // [parity][16] -an_t*exp(-an_s), parity-pair-packed
#define O_ASUM  4320   // sum(an_s)

typedef unsigned long long u64;

// Scratch (__device__ globals: allocation-free)
__device__ float g_packed[CC * KK * PK];   // ~8.9 MB
__device__ float g_E[NN * CC];             // [n][c] = exp(logq)
__device__ float g_G[NN * CC];
__device__ float g_A[NN * CC];
__device__ float g_den[CC];                // raw L1 sums (zeroed by pack)

// ---------------------------------------------------------------------------
// f32x2 packed-math helpers
// ---------------------------------------------------------------------------
__device__ __forceinline__ u64 fma2(u64 a, u64 b, u64 c) {
    u64 d;
    asm("fma.rn.f32x2 %0, %1, %2, %3;" : "=l"(d) : "l"(a), "l"(b), "l"(c));
    return d;
}
__device__ __forceinline__ u64 add2(u64 a, u64 b) {
    u64 d;
    asm("add.rn.f32x2 %0, %1, %2;" : "=l"(d) : "l"(a), "l"(b));
    return d;
}
__device__ __forceinline__ u64 mul2(u64 a, u64 b) {
    u64 d;
    asm("mul.rn.f32x2 %0, %1, %2;" : "=l"(d) : "l"(a), "l"(b));
    return d;
}
__device__ __forceinline__ u64 packf2(float lo, float hi) {
    u64 d;
    asm("mov.b64 %0, {%1, %2};" : "=l"(d) : "f"(lo), "f"(hi));
    return d;
}
__device__ __forceinline__ float2 unpackf2(u64 v) {
    float2 r;
    asm("mov.b64 {%0, %1}, %2;" : "=f"(r.x), "=f"(r.y) : "l"(v));
    return r;
}

// ---------------------------------------------------------------------------
// cp.async helpers
// ---------------------------------------------------------------------------
__device__ __forceinline__ void cp_async16(void* smem, const void* gmem) {
    unsigned s = (unsigned)__cvta_generic_to_shared(smem);
    asm volatile("cp.async.cg.shared.global [%0], [%1], 16;\n" :: "r"(s), "l"(gmem) : "memory");
}
__device__ __forceinline__ void cp_commit() {
    asm volatile("cp.async.commit_group;\n" ::: "memory");
}
__device__ __forceinline__ void cp_wait0() {
    asm volatile("cp.async.wait_group 0;\n" ::: "memory");
}

// No-op kernels: keep flow_kernel in the ncu-profiled (4th) launch slot.
__global__ void nop_kernel() {}

// ---------------------------------------------------------------------------
// Kernel 1: pack weights + parity-packed ActNorm tables + zero g_den
// ---------------------------------------------------------------------------
__global__ void pack_kernel(const float* __restrict__ sW1, const float* __restrict__ sb1,
                            const float* __restrict__ sW2, const float* __restrict__ sb2,
                            const float* __restrict__ tW1, const float* __restrict__ tb1,
                            const float* __restrict__ tW2, const float* __restrict__ tb2,
                            const float* __restrict__ ans, const float* __restrict__ ant) {
    int ck = blockIdx.x;           // c*64 + k
    int k  = ck & 63;
    int p  = k & 1;                // masked dims: d%2 == k%2
    float* dst = g_packed + (size_t)ck * PK;
    const float* w1s = sW1 + (size_t)ck * 2048;
    const float* w2s = sW2 + (size_t)ck * 2048;
    const float* w1t = tW1 + (size_t)ck * 2048;
    const float* w2t = tW2 + (size_t)ck * 2048;

    if (blockIdx.x == 0 && threadIdx.x < CC) g_den[threadIdx.x] = 0.f;

    for (int t = threadIdx.x; t < 1024; t += blockDim.x) {
        int j = t >> 4, i = t & 15;
        int di = 2 * i + p;          // masked input dim
        int du = 2 * i + 1 - p;      // unmasked output dim
        dst[O_W1S + t] = w1s[j * 32 + di];
        dst[O_W1T + t] = w1t[j * 32 + di];
        dst[O_W2S + t] = w2s[du * 64 + j];
        dst[O_W2T + t] = w2t[du * 64 + j];
    }
    for (int t = threadIdx.x; t < 64; t += blockDim.x) {
        dst[O_B1S + t] = sb1[ck * 64 + t];
        dst[O_B1T + t] = tb1[ck * 64 + t];
    }
    for (int t = threadIdx.x; t < 16; t += blockDim.x) {
        int du = 2 * t + 1 - p;
        dst[O_B2S + t] = sb2[ck * 32 + du];
        dst[O_B2T + t] = tb2[ck * 32 + du];
    }
    // ActNorm tables, parity-pair-packed: table[par][2q+lo] = dim 4q+2*lo+par
    for (int t = threadIdx.x; t < 32; t += blockDim.x) {
        int par = t >> 4, qi = t & 15;
        int q = qi >> 1, lo = qi & 1;
        int d = 4 * q + 2 * lo + par;
        float e = expf(-ans[ck * 32 + d]);
        dst[O_ANE + t] = e;
        dst[O_ANB + t] = -ant[ck * 32 + d] * e;
    }
    if (threadIdx.x == 0) {
        float s = 0.f;
        for (int d = 0; d < 32; d++) s += ans[ck * 32 + d];
        dst[O_ASUM] = s;
        for (int q = O_ASUM + 1; q < PK; q++) dst[q] = 0.f;
    }
}

// ---------------------------------------------------------------------------
// Kernel 2: flow chain — z kept as parity-packed f32x2; W1 software-pipelined
// zm = masked-parity pairs (MLP input), zu = unmasked-parity pairs (updated).
// ---------------------------------------------------------------------------
template <int P>
__device__ __forceinline__ void layer_step(const float* sw, int wo, int net,
                                           u64* zm0, u64* zu0, u64* zm1, u64* zu1,
                                           float& ld0, float& ld1) {
    float asum = sw[O_ASUM];
    ld0 -= asum; ld1 -= asum;

    // ActNorm inverse on packed pairs: 32 fma2 total (both nodes)
    {
        const float* aneM = sw + O_ANE + P * 16;
        const float* aneU = sw + O_ANE + (1 - P) * 16;
        const float* anbM = sw + O_ANB + P * 16;
        const float* anbU = sw + O_ANB + (1 - P) * 16;
#pragma unroll
        for (int h = 0; h < 4; h++) {
            ulonglong2 eM = *reinterpret_cast<const ulonglong2*>(aneM + h * 4);
            ulonglong2 bM = *reinterpret_cast<const ulonglong2*>(anbM + h * 4);
            ulonglong2 eU = *reinterpret_cast<const ulonglong2*>(aneU + h * 4);
            ulonglong2 bU = *reinterpret_cast<const ulonglong2*>(anbU + h * 4);
            zm0[2 * h]     = fma2(zm0[2 * h],     eM.x, bM.x);
            zm0[2 * h + 1] = fma2(zm0[2 * h + 1], eM.y, bM.y);
            zm1[2 * h]     = fma2(zm1[2 * h],     eM.x, bM.x);
            zm1[2 * h + 1] = fma2(zm1[2 * h + 1], eM.y, bM.y);
            zu0[2 * h]     = fma2(zu0[2 * h],     eU.x, bU.x);
            zu0[2 * h + 1] = fma2(zu0[2 * h + 1], eU.y, bU.y);
            zu1[2 * h]     = fma2(zu1[2 * h],     eU.x, bU.x);
            zu1[2 * h + 1] = fma2(zu1[2 * h + 1], eU.y, bU.y);
        }
    }

    // Accumulators (this thread's net, both nodes) init from output biases
    const float* b2 = sw + O_B2S + wo;
    u64 a0[8], a1[8];
#pragma unroll
    for (int q = 0; q < 4; q++) {
        ulonglong2 a = *reinterpret_cast<const ulonglong2*>(b2 + q * 4);
        a0[2 * q] = a.x; a0[2 * q + 1] = a.y;
        a1[2 * q] = a.x; a1[2 * q + 1] = a.y;
    }

    const float* w1 = sw + O_W1S + wo;
    const float* w2 = sw + O_W2S + wo;
    const float* b1 = sw + O_B1S + wo;

    // W1 double-buffer prologue (block j2=0)
    ulonglong2 wA0 = *reinterpret_cast<const ulonglong2*>(w1);
    ulonglong2 wB0 = *reinterpret_cast<const ulonglong2*>(w1 + 4);
    ulonglong2 wC0 = *reinterpret_cast<const ulonglong2*>(w1 + 8);
    ulonglong2 wD0 = *reinterpret_cast<const ulonglong2*>(w1 + 12);
    ulonglong2 wA1 = *reinterpret_cast<const ulonglong2*>(w1 + 16);
    ulonglong2 wB1 = *reinterpret_cast<const ulonglong2*>(w1 + 20);
    ulonglong2 wC1 = *reinterpret_cast<const ulonglong2*>(w1 + 24);
    ulonglong2 wD1 = *reinterpret_cast<const ulonglong2*>(w1 + 28);
    float2 bv = *reinterpret_cast<const float2*>(b1);

#pragma unroll 2
    for (int j2 = 0; j2 < 64; j2 += 2) {
        // W2 for current block (consumed late: latency covered by dot phase)
        ulonglong2 vA0 = *reinterpret_cast<const ulonglong2*>(w2 + j2 * 16);
        ulonglong2 vB0 = *reinterpret_cast<const ulonglong2*>(w2 + j2 * 16 + 4);
        ulonglong2 vC0 = *reinterpret_cast<const ulonglong2*>(w2 + j2 * 16 + 8);
        ulonglong2 vD0 = *reinterpret_cast<const ulonglong2*>(w2 + j2 * 16 + 12);
        ulonglong2 vA1 = *reinterpret_cast<const ulonglong2*>(w2 + j2 * 16 + 16);
        ulonglong2 vB1 = *reinterpret_cast<const ulonglong2*>(w2 + j2 * 16 + 20);
        ulonglong2 vC1 = *reinterpret_cast<const ulonglong2*>(w2 + j2 * 16 + 24);
        ulonglong2 vD1 = *reinterpret_cast<const ulonglong2*>(w2 + j2 * 16 + 28);

        // Prefetch next W1 block + b1 (hidden behind this block's compute)
        ulonglong2 nA0, nB0, nC0, nD0, nA1, nB1, nC1, nD1;
        float2 nbv;
        if (j2 < 62) {
            const float* w1n = w1 + (j2 + 2) * 16;
            nA0 = *reinterpret_cast<const ulonglong2*>(w1n);
            nB0 = *reinterpret_cast<const ulonglong2*>(w1n + 4);
            nC0 = *reinterpret_cast<const ulonglong2*>(w1n + 8);
            nD0 = *reinterpret_cast<const ulonglong2*>(w1n + 12);
            nA1 = *reinterpret_cast<const ulonglong2*>(w1n + 16);
            nB1 = *reinterpret_cast<const ulonglong2*>(w1n + 20);
            nC1 = *reinterpret_cast<const ulonglong2*>(w1n + 24);
            nD1 = *reinterpret_cast<const ulonglong2*>(w1n + 28);
            nbv = *reinterpret_cast<const float2*>(b1 + j2 + 2);
        }

        // ---- dot chains (zm used directly; no marshalling) ----
        u64 p00 = fma2(wA0.x, zm0[0], 0ull), p01 = fma2(wA0.y, zm0[1], 0ull);
        u64 q00 = fma2(wA0.x, zm1[0], 0ull), q01 = fma2(wA0.y, zm1[1], 0ull);
        u64 p10 = fma2(wA1.x, zm0[0], 0ull), p11 = fma2(wA1.y, zm0[1], 0ull);
        u64 q10 = fma2(wA1.x, zm1[0], 0ull), q11 = fma2(wA1.y, zm1[1], 0ull);
        p00 = fma2(wB0.x, zm0[2], p00); p01 = fma2(wB0.y, zm0[3], p01);
        q00 = fma2(wB0.x, zm1[2], q00); q01 = fma2(wB0.y, zm1[3], q01);
        p10 = fma2(wB1.x, zm0[2], p10); p11 = fma2(wB1.y, zm0[3], p11);
        q10 = fma2(wB1.x, zm1[2], q10); q11 = fma2(wB1.y, zm1[3], q11);
        p00 = fma2(wC0.x, zm0[4], p00); p01 = fma2(wC0.y, zm0[5], p01);
        q00 = fma2(wC0.x, zm1[4], q00); q01 = fma2(wC0.y, zm1[5], q01);
        p10 = fma2(wC1.x, zm0[4], p10); p11 = fma2(wC1.y, zm0[5], p11);
        q10 = fma2(wC1.x, zm1[4], q10); q11 = fma2(wC1.y, zm1[5], q11);
        p00 = fma2(wD0.x, zm0[6], p00); p01 = fma2(wD0.y, zm0[7], p01);
        q00 = fma2(wD0.x, zm1[6], q00); q01 = fma2(wD0.y, zm1[7], q01);
        p10 = fma2(wD1.x, zm0[6], p10); p11 = fma2(wD1.y, zm0[7], p11);
        q10 = fma2(wD1.x, zm1[6], q10); q11 = fma2(wD1.y, zm1[7], q11);

        // ---- 4 hidden activations ----
        float2 pp0 = unpackf2(add2(p00, p01));
        float2 qq0 = unpackf2(add2(q00, q01));
        float2 pp1 = unpackf2(add2(p10, p11));
        float2 qq1 = unpackf2(add2(q10, q11));
        float h00 = fmaxf(bv.x + (pp0.x + pp0.y), 0.f);
        float h01 = fmaxf(bv.x + (qq0.x + qq0.y), 0.f);
        float h10 = fmaxf(bv.y + (pp1.x + pp1.y), 0.f);
        float h11 = fmaxf(bv.y + (qq1.x + qq1.y), 0.f);
        u64 hh00 = packf2(h00, h00);
        u64 hh01 = packf2(h01, h01);
        u64 hh10 = packf2(h10, h10);
        u64 hh11 = packf2(h11, h11);

        // ---- scatters ----
        a0[0] = fma2(vA0.x, hh00, a0[0]); a0[1] = fma2(vA0.y, hh00, a0[1]);
        a0[2] = fma2(vB0.x, hh00, a0[2]); a0[3] = fma2(vB0.y, hh00, a0[3]);
        a0[4] = fma2(vC0.x, hh00, a0[4]); a0[5] = fma2(vC0.y, hh00, a0[5]);
        a0[6] = fma2(vD0.x, hh00, a0[6]); a0[7] = fma2(vD0.y, hh00, a0[7]);

        a1[0] = fma2(vA0.x, hh01, a1[0]); a1[1] = fma2(vA0.y, hh01, a1[1]);
        a1[2] = fma2(vB0.x, hh01, a1[2]); a1[3] = fma2(vB0.y, hh01, a1[3]);
        a1[4] = fma2(vC0.x, hh01, a1[4]); a1[5] = fma2(vC0.y, hh01, a1[5]);
        a1[6] = fma2(vD0.x, hh01, a1[6]); a1[7] = fma2(vD0.y, hh01, a1[7]);

        a0[0] = fma2(vA1.x, hh10, a0[0]); a0[1] = fma2(vA1.y, hh10, a0[1]);
        a0[2] = fma2(vB1.x, hh10, a0[2]); a0[3] = fma2(vB1.y, hh10, a0[3]);
        a0[4] = fma2(vC1.x, hh10, a0[4]); a0[5] = fma2(vC1.y, hh10, a0[5]);
        a0[6] = fma2(vD1.x, hh10, a0[6]); a0[7] = fma2(vD1.y, hh10, a0[7]);

        a1[0] = fma2(vA1.x, hh11, a1[0]); a1[1] = fma2(vA1.y, hh11, a1[1]);
        a1[2] = fma2(vB1.x, hh11, a1[2]); a1[3] = fma2(vB1.y, hh11, a1[3]);
        a1[4] = fma2(vC1.x, hh11, a1[4]); a1[5] = fma2(vC1.y, hh11, a1[5]);
        a1[6] = fma2(vD1.x, hh11, a1[6]); a1[7] = fma2(vD1.y, hh11, a1[7]);

        // rotate W1 double-buffer
        wA0 = nA0; wB0 = nB0; wC0 = nC0; wD0 = nD0;
        wA1 = nA1; wB1 = nB1; wC1 = nC1; wD1 = nD1;
        bv = nbv;
    }

    // Exchange nets; coupling on packed zu.
    const u64 NEG1 = packf2(-1.f, -1.f);
#pragma unroll
    for (int q = 0; q < 8; q++) {
        u64 o0 = __shfl_xor_sync(0xffffffffu, a0[q], 1);
        u64 o1 = __shfl_xor_sync(0xffffffffu, a1[q], 1);
        u64 sv0 = net ? o0 : a0[q];
        u64 tv0 = net ? a0[q] : o0;
        u64 sv1 = net ? o1 : a1[q];
        u64 tv1 = net ? a1[q] : o1;
        float2 s0 = unpackf2(sv0);
        float2 s1 = unpackf2(sv1);
        u64 e0 = packf2(__expf(-s0.x), __expf(-s0.y));
        u64 e1 = packf2(__expf(-s1.x), __expf(-s1.y));
        zu0[q] = mul2(fma2(tv0, NEG1, zu0[q]), e0);
        zu1[q] = mul2(fma2(tv1, NEG1, zu1[q]), e1);
        ld0 -= s0.x + s0.y;
        ld1 -= s1.x + s1.y;
    }
}

__device__ __forceinline__ void prefetch_layer(float* dst, const float* src) {
    int t = threadIdx.x;
#pragma unroll
    for (int q = 0; q < 9; q++) {
        int idx = t + q * 128;          // 16B units; total PK/4 = 1088
        if (idx < PK / 4) cp_async16(dst + idx * 4, src + idx * 4);
    }
}

__global__ void __launch_bounds__(128, 1)
flow_kernel(const float* __restrict__ nodes, const float* __restrict__ loc,
            const float* __restrict__ lsc) {
    __shared__ __align__(16) float sw[2][PK];
    const int c    = blockIdx.y;
    const int net  = threadIdx.x & 1;                 // 0 = s-net, 1 = t-net
    const int pair = threadIdx.x >> 1;                // 0..63
    const int n0   = blockIdx.x * 128 + pair;
    const int n1   = n0 + 64;
    const int wo   = net * NETOFF;

    // z stored as parity-packed pairs: zp0 = dims (4q, 4q+2), zp1 = (4q+1, 4q+3)
    u64 zp0_0[8], zp1_0[8], zp0_1[8], zp1_1[8];
#pragma unroll
    for (int q = 0; q < 8; q++) {
        float4 v0 = *reinterpret_cast<const float4*>(nodes + n0 * 32 + q * 4);
        zp0_0[q] = packf2(v0.x, v0.z);
        zp1_0[q] = packf2(v0.y, v0.w);
        float4 v1 = *reinterpret_cast<const float4*>(nodes + n1 * 32 + q * 4);
        zp0_1[q] = packf2(v1.x, v1.z);
        zp1_1[q] = packf2(v1.y, v1.w);
    }
    float ld0 = 0.f, ld1 = 0.f;

    const float* gp = g_packed + (size_t)c * (KK * PK);
    prefetch_layer(sw[1], gp + 63 * PK);   // layer 63 -> buf (63&1)=1
    cp_commit();

    for (int it = 0; it < 64; it++) {
        const int k = 63 - it;
        const int b = k & 1;
        cp_wait0();
        __syncthreads();
        if (it < 63) prefetch_layer(sw[b ^ 1], gp + (k - 1) * PK);
        cp_commit();
        if (b) layer_step<1>(sw[b], wo, net, zp1_0, zp0_0, zp1_1, zp0_1, ld0, ld1);
        else   layer_step<0>(sw[b], wo, net, zp0_0, zp1_0, zp0_1, zp1_1, ld0, ld1);
        // next iteration's top __syncthreads guards buffer reuse
    }

    // DiagGaussian log prob + exp + block L1-sum
    float lq0 = ld0 - 29.40603306254953f;    // 0.5 * D * log(2*pi)
    float lq1 = ld1 - 29.40603306254953f;
    const float* lc = loc + c * 32;
    const float* ls = lsc + c * 32;
#pragma unroll
    for (int q = 0; q < 8; q++) {
        float2 a0 = unpackf2(zp0_0[q]);   // dims 4q, 4q+2 node0
        float2 b0 = unpackf2(zp1_0[q]);   // dims 4q+1, 4q+3 node0
        float2 a1 = unpackf2(zp0_1[q]);
        float2 b1 = unpackf2(zp1_1[q]);
        int d0 = 4 * q, d1 = 4 * q + 1, d2 = 4 * q + 2, d3 = 4 * q + 3;
        float l0 = ls[d0], l1 = ls[d1], l2 = ls[d2], l3 = ls[d3];
        float e0 = __expf(-l0), e1 = __expf(-l1), e2 = __expf(-l2), e3 = __expf(-l3);
        float u;
        u = (a0.x - lc[d0]) * e0; lq0 -= l0 + 0.5f * u * u;
        u = (b0.x - lc[d1]) * e1; lq0 -= l1 + 0.5f * u * u;
        u = (a0.y - lc[d2]) * e2; lq0 -= l2 + 0.5f * u * u;
        u = (b0.y - lc[d3]) * e3; lq0 -= l3 + 0.5f * u * u;
        u = (a1.x - lc[d0]) * e0; lq1 -= l0 + 0.5f * u * u;
        u = (b1.x - lc[d1]) * e1; lq1 -= l1 + 0.5f * u * u;
        u = (a1.y - lc[d2]) * e2; lq1 -= l2 + 0.5f * u * u;
        u = (b1.y - lc[d3]) * e3; lq1 -= l3 + 0.5f * u * u;
    }
    float e0 = expf(lq0);
    float e1 = expf(lq1);
    if (net == 0) {
        g_E[n0 * CC + c] = e0;
        g_E[n1 * CC + c] = e1;
    }
    __syncthreads();                       // done with sw weights
    float* red = sw[0];
    red[threadIdx.x] = (net == 0) ? (e0 + e1) : 0.f;
    __syncthreads();
    for (int w = 64; w > 0; w >>= 1) {
        if (threadIdx.x < w) red[threadIdx.x] += red[threadIdx.x + w];
        __syncthreads();
    }
    if (threadIdx.x == 0) atomicAdd(&g_den[c], red[0]);
}

// ---------------------------------------------------------------------------
// Kernel 5: G = Bm normalized (clamped), A = S-weighted; S computed in-kernel
// ---------------------------------------------------------------------------
__global__ void ga_kernel(const float* __restrict__ S_unc) {
    __shared__ float sS[64];
    __shared__ float sden[8];
    __shared__ float stot;
    if (threadIdx.x < 64) sS[threadIdx.x] = expf(S_unc[threadIdx.x]);
    if (threadIdx.x >= 64 && threadIdx.x < 72)
        sden[threadIdx.x - 64] = fmaxf(g_den[threadIdx.x - 64], 1e-12f);
    __syncthreads();
    if (threadIdx.x == 0) {
        float s = 0.f;
        for (int i = 0; i < 64; i++) s += sS[i];
        stot = 1.f / s;
    }
    __syncthreads();
    float stot_l = stot;
    int j = blockIdx.x * 256 + threadIdx.x;
    float g[8];
#pragma unroll
    for (int c = 0; c < 8; c++) g[c] = g_E[j * CC + c] / sden[c];
#pragma unroll
    for (int c = 0; c < 8; c++) g_G[j * CC + c] = g[c];
#pragma unroll
    for (int c = 0; c < 8; c++) {
        float a = 0.f;
#pragma unroll
        for (int c2 = 0; c2 < 8; c2++) a = fmaf(sS[c * 8 + c2] * stot_l, g[c2], a);
        g_A[j * CC + c] = a;
    }
}

// ---------------------------------------------------------------------------
// Kernel 6: out[i][j] = sum_c G[i][c] * A[j][c]   (rank-8, 64x64 tiles)
// ---------------------------------------------------------------------------
__global__ void __launch_bounds__(256) outer_kernel(float* __restrict__ out) {
    __shared__ float Gs[64][8];
    __shared__ float As[64][8];
    int i0 = blockIdx.y * 64, j0 = blockIdx.x * 64;
    int t = threadIdx.x;
    for (int q = t; q < 512; q += 256) {
        ((float*)Gs)[q] = g_G[i0 * 8 + q];
        ((float*)As)[q] = g_A[j0 * 8 + q];
    }
    __syncthreads();
    int tx = t & 15, ty = t >> 4;
    float gr[4][8], ar[4][8];
#pragma unroll
    for (int r = 0; r < 4; r++)
#pragma unroll
        for (int c = 0; c < 8; c++) {
            gr[r][c] = Gs[ty * 4 + r][c];
            ar[r][c] = As[tx * 4 + r][c];
        }
#pragma unroll
    for (int r = 0; r < 4; r++) {
        float4 o;
        float acc[4] = {0.f, 0.f, 0.f, 0.f};
#pragma unroll
        for (int c = 0; c < 8; c++) {
            acc[0] = fmaf(gr[r][c], ar[0][c], acc[0]);
            acc[1] = fmaf(gr[r][c], ar[1][c], acc[1]);
            acc[2] = fmaf(gr[r][c], ar[2][c], acc[2]);
            acc[3] = fmaf(gr[r][c], ar[3][c], acc[3]);
        }
        o.x = acc[0]; o.y = acc[1]; o.z = acc[2]; o.w = acc[3];
        *reinterpret_cast<float4*>(out + (size_t)(i0 + ty * 4 + r) * NN + j0 + tx * 4) = o;
    }
}

// ---------------------------------------------------------------------------
extern "C" void kernel_launch(void* const* d_in, const int* in_sizes, int n_in,
                              void* d_out, int out_size) {
    const float* nodes = (const float*)d_in[0];
    const float* sW1   = (const float*)d_in[1];
    const float* sb1   = (const float*)d_in[2];
    const float* sW2   = (const float*)d_in[3];
    const float* sb2   = (const float*)d_in[4];
    const float* tW1   = (const float*)d_in[5];
    const float* tb1   = (const float*)d_in[6];
    const float* tW2   = (const float*)d_in[7];
    const float* tb2   = (const float*)d_in[8];
    const float* ans   = (const float*)d_in[9];
    const float* ant   = (const float*)d_in[10];
    const float* loc   = (const float*)d_in[11];
    const float* lsc   = (const float*)d_in[12];
    const float* Sunc  = (const float*)d_in[13];
    float* out = (float*)d_out;

    pack_kernel<<<CC * KK, 256>>>(sW1, sb1, sW2, sb2, tW1, tb1, tW2, tb2, ans, ant);
    // Keep flow_kernel in the ncu-profiled (4th) launch slot.
    nop_kernel<<<1, 32>>>();
    nop_kernel<<<1, 32>>>();
    flow_kernel<<<dim3(NN / 128, CC), 128>>>(nodes, loc, lsc);
    ga_kernel<<<NN / 256, 256>>>(Sunc);
    outer_kernel<<<dim3(NN / 64, NN / 64), 256>>>(out);
}

// round 14
// speedup vs baseline: 1.1295x; 1.1295x over previous
#include <cuda_runtime.h>
#include <cuda_bf16.h>
#include <cstdint>

// Problem constants
#define CC 8
#define KK 64
#define DD 32
#define NN 2048

// Packed per-(c,k) weight block layout (floats) — R4 layout
#define PK      4352
#define NETOFF  2128
#define O_W1S   0      // [64][16]
#define O_B1S   1024   // [64]
#define O_W2S   1088   // [64][16]  transposed: [j][i] = W2[ud(i)][j]
#define O_B2S   2112   // [16]
#define O_W1T   2128
#define O_B1T   3152
#define O_W2T   3216
#define O_B2T   4240
#define O_ANE   4256   // [32] exp(-an_s)
#define O_ANB   4288   // [32] -an_t * exp(-an_s)
#define O_ASUM  4320   // sum(an_s)

typedef unsigned long long u64;

// Scratch (__device__ globals: allocation-free)
__device__ float g_packed[CC * KK * PK];   // ~8.9 MB
__device__ float g_E[NN * CC];             // [n][c] = exp(logq)
__device__ float g_G[NN * CC];
__device__ float g_A[NN * CC];
__device__ float g_den[CC];                // raw L1 sums (zeroed by pack)

// ---------------------------------------------------------------------------
// f32x2 packed-math helpers
// ---------------------------------------------------------------------------
__device__ __forceinline__ u64 fma2(u64 a, u64 b, u64 c) {
    u64 d;
    asm("fma.rn.f32x2 %0, %1, %2, %3;" : "=l"(d) : "l"(a), "l"(b), "l"(c));
    return d;
}
__device__ __forceinline__ u64 add2(u64 a, u64 b) {
    u64 d;
    asm("add.rn.f32x2 %0, %1, %2;" : "=l"(d) : "l"(a), "l"(b));
    return d;
}
__device__ __forceinline__ u64 packf2(float lo, float hi) {
    u64 d;
    asm("mov.b64 %0, {%1, %2};" : "=l"(d) : "f"(lo), "f"(hi));
    return d;
}
__device__ __forceinline__ float2 unpackf2(u64 v) {
    float2 r;
    asm("mov.b64 {%0, %1}, %2;" : "=f"(r.x), "=f"(r.y) : "l"(v));
    return r;
}

// ---------------------------------------------------------------------------
// cp.async helpers
// ---------------------------------------------------------------------------
__device__ __forceinline__ void cp_async16(void* smem, const void* gmem) {
    unsigned s = (unsigned)__cvta_generic_to_shared(smem);
    asm volatile("cp.async.cg.shared.global [%0], [%1], 16;\n" :: "r"(s), "l"(gmem) : "memory");
}
__device__ __forceinline__ void cp_commit() {
    asm volatile("cp.async.commit_group;\n" ::: "memory");
}
__device__ __forceinline__ void cp_wait0() {
    asm volatile("cp.async.wait_group 0;\n" ::: "memory");
}

// No-op kernels: keep flow_kernel in the ncu-profiled (4th) launch slot.
__global__ void nop_kernel() {}

// ---------------------------------------------------------------------------
// Kernel 1: pack weights (R4 layout) + zero g_den
// ---------------------------------------------------------------------------
__global__ void pack_kernel(const float* __restrict__ sW1, const float* __restrict__ sb1,
                            const float* __restrict__ sW2, const float* __restrict__ sb2,
                            const float* __restrict__ tW1, const float* __restrict__ tb1,
                            const float* __restrict__ tW2, const float* __restrict__ tb2,
                            const float* __restrict__ ans, const float* __restrict__ ant) {
    int ck = blockIdx.x;           // c*64 + k
    int k  = ck & 63;
    int p  = k & 1;                // masked dims: d%2 == k%2
    float* dst = g_packed + (size_t)ck * PK;
    const float* w1s = sW1 + (size_t)ck * 2048;
    const float* w2s = sW2 + (size_t)ck * 2048;
    const float* w1t = tW1 + (size_t)ck * 2048;
    const float* w2t = tW2 + (size_t)ck * 2048;

    if (blockIdx.x == 0 && threadIdx.x < CC) g_den[threadIdx.x] = 0.f;

    for (int t = threadIdx.x; t < 1024; t += blockDim.x) {
        int j = t >> 4, i = t & 15;
        int di = 2 * i + p;          // masked input dim
        int du = 2 * i + 1 - p;      // unmasked output dim
        dst[O_W1S + t] = w1s[j * 32 + di];
        dst[O_W1T + t] = w1t[j * 32 + di];
        dst[O_W2S + t] = w2s[du * 64 + j];
        dst[O_W2T + t] = w2t[du * 64 + j];
    }
    for (int t = threadIdx.x; t < 64; t += blockDim.x) {
        dst[O_B1S + t] = sb1[ck * 64 + t];
        dst[O_B1T + t] = tb1[ck * 64 + t];
    }
    for (int t = threadIdx.x; t < 16; t += blockDim.x) {
        int du = 2 * t + 1 - p;
        dst[O_B2S + t] = sb2[ck * 32 + du];
        dst[O_B2T + t] = tb2[ck * 32 + du];
    }
    for (int t = threadIdx.x; t < 32; t += blockDim.x) {
        float e = expf(-ans[ck * 32 + t]);
        dst[O_ANE + t] = e;
        dst[O_ANB + t] = -ant[ck * 32 + t] * e;   // z' = fma(z, e, -t*e)
    }
    if (threadIdx.x == 0) {
        float s = 0.f;
        for (int d = 0; d < 32; d++) s += ans[ck * 32 + d];
        dst[O_ASUM] = s;
        for (int q = O_ASUM + 1; q < PK; q++) dst[q] = 0.f;
    }
}

// ---------------------------------------------------------------------------
// Kernel 2: flow chain — R11 structure, unroll 4, packed log-det accumulation
// ---------------------------------------------------------------------------
template <int P>
__device__ __forceinline__ void layer_step(const float* sw, int wo, int net,
                                           float* z0, float* z1,
                                           float& ld0, float& ld1,
                                           u64& lsum0, u64& lsum1) {
    float asum = sw[O_ASUM];
    ld0 -= asum; ld1 -= asum;
    // ActNorm inverse — vectorized param loads (float4)
#pragma unroll
    for (int q = 0; q < 8; q++) {
        float4 e4 = *reinterpret_cast<const float4*>(sw + O_ANE + q * 4);
        float4 b4 = *reinterpret_cast<const float4*>(sw + O_ANB + q * 4);
        z0[4 * q + 0] = fmaf(z0[4 * q + 0], e4.x, b4.x);
        z0[4 * q + 1] = fmaf(z0[4 * q + 1], e4.y, b4.y);
        z0[4 * q + 2] = fmaf(z0[4 * q + 2], e4.z, b4.z);
        z0[4 * q + 3] = fmaf(z0[4 * q + 3], e4.w, b4.w);
        z1[4 * q + 0] = fmaf(z1[4 * q + 0], e4.x, b4.x);
        z1[4 * q + 1] = fmaf(z1[4 * q + 1], e4.y, b4.y);
        z1[4 * q + 2] = fmaf(z1[4 * q + 2], e4.z, b4.z);
        z1[4 * q + 3] = fmaf(z1[4 * q + 3], e4.w, b4.w);
    }

    // Masked inputs as packed f32x2: pair q = (z[4q+P], z[4q+2+P])
    u64 xm0[8], xm1[8];
#pragma unroll
    for (int q = 0; q < 8; q++) {
        xm0[q] = packf2(z0[4 * q + P], z0[4 * q + 2 + P]);
        xm1[q] = packf2(z1[4 * q + P], z1[4 * q + 2 + P]);
    }

    // Accumulators for this thread's net, both nodes, init from output biases
    const float* b2 = sw + O_B2S + wo;
    u64 a0[8], a1[8];
#pragma unroll
    for (int q = 0; q < 4; q++) {
        ulonglong2 a = *reinterpret_cast<const ulonglong2*>(b2 + q * 4);
        a0[2 * q] = a.x; a0[2 * q + 1] = a.y;
        a1[2 * q] = a.x; a1[2 * q + 1] = a.y;
    }

    const float* w1 = sw + O_W1S + wo;
    const float* w2 = sw + O_W2S + wo;
    const float* b1 = sw + O_B1S + wo;

#pragma unroll 4
    for (int j2 = 0; j2 < 64; j2 += 2) {
        float2 bv = *reinterpret_cast<const float2*>(b1 + j2);
        // ---- load ALL weights for both j up front ----
        ulonglong2 wA0 = *reinterpret_cast<const ulonglong2*>(w1 + j2 * 16);
        ulonglong2 wB0 = *reinterpret_cast<const ulonglong2*>(w1 + j2 * 16 + 4);
        ulonglong2 wC0 = *reinterpret_cast<const ulonglong2*>(w1 + j2 * 16 + 8);
        ulonglong2 wD0 = *reinterpret_cast<const ulonglong2*>(w1 + j2 * 16 + 12);
        ulonglong2 wA1 = *reinterpret_cast<const ulonglong2*>(w1 + j2 * 16 + 16);
        ulonglong2 wB1 = *reinterpret_cast<const ulonglong2*>(w1 + j2 * 16 + 20);
        ulonglong2 wC1 = *reinterpret_cast<const ulonglong2*>(w1 + j2 * 16 + 24);
        ulonglong2 wD1 = *reinterpret_cast<const ulonglong2*>(w1 + j2 * 16 + 28);
        ulonglong2 vA0 = *reinterpret_cast<const ulonglong2*>(w2 + j2 * 16);
        ulonglong2 vB0 = *reinterpret_cast<const ulonglong2*>(w2 + j2 * 16 + 4);
        ulonglong2 vC0 = *reinterpret_cast<const ulonglong2*>(w2 + j2 * 16 + 8);
        ulonglong2 vD0 = *reinterpret_cast<const ulonglong2*>(w2 + j2 * 16 + 12);
        ulonglong2 vA1 = *reinterpret_cast<const ulonglong2*>(w2 + j2 * 16 + 16);
        ulonglong2 vB1 = *reinterpret_cast<const ulonglong2*>(w2 + j2 * 16 + 20);
        ulonglong2 vC1 = *reinterpret_cast<const ulonglong2*>(w2 + j2 * 16 + 24);
        ulonglong2 vD1 = *reinterpret_cast<const ulonglong2*>(w2 + j2 * 16 + 28);

        // ---- dot chains ----
        u64 p00 = fma2(wA0.x, xm0[0], 0ull), p01 = fma2(wA0.y, xm0[1], 0ull);
        u64 q00 = fma2(wA0.x, xm1[0], 0ull), q01 = fma2(wA0.y, xm1[1], 0ull);
        u64 p10 = fma2(wA1.x, xm0[0], 0ull), p11 = fma2(wA1.y, xm0[1], 0ull);
        u64 q10 = fma2(wA1.x, xm1[0], 0ull), q11 = fma2(wA1.y, xm1[1], 0ull);
        p00 = fma2(wB0.x, xm0[2], p00); p01 = fma2(wB0.y, xm0[3], p01);
        q00 = fma2(wB0.x, xm1[2], q00); q01 = fma2(wB0.y, xm1[3], q01);
        p10 = fma2(wB1.x, xm0[2], p10); p11 = fma2(wB1.y, xm0[3], p11);
        q10 = fma2(wB1.x, xm1[2], q10); q11 = fma2(wB1.y, xm1[3], q11);
        p00 = fma2(wC0.x, xm0[4], p00); p01 = fma2(wC0.y, xm0[5], p01);
        q00 = fma2(wC0.x, xm1[4], q00); q01 = fma2(wC0.y, xm1[5], q01);
        p10 = fma2(wC1.x, xm0[4], p10); p11 = fma2(wC1.y, xm0[5], p11);
        q10 = fma2(wC1.x, xm1[4], q10); q11 = fma2(wC1.y, xm1[5], q11);
        p00 = fma2(wD0.x, xm0[6], p00); p01 = fma2(wD0.y, xm0[7], p01);
        q00 = fma2(wD0.x, xm1[6], q00); q01 = fma2(wD0.y, xm1[7], q01);
        p10 = fma2(wD1.x, xm0[6], p10); p11 = fma2(wD1.y, xm0[7], p11);
        q10 = fma2(wD1.x, xm1[6], q10); q11 = fma2(wD1.y, xm1[7], q11);

        // ---- 4 hidden activations ----
        float2 pp0 = unpackf2(add2(p00, p01));
        float2 qq0 = unpackf2(add2(q00, q01));
        float2 pp1 = unpackf2(add2(p10, p11));
        float2 qq1 = unpackf2(add2(q10, q11));
        float h00 = fmaxf(bv.x + (pp0.x + pp0.y), 0.f);
        float h01 = fmaxf(bv.x + (qq0.x + qq0.y), 0.f);
        float h10 = fmaxf(bv.y + (pp1.x + pp1.y), 0.f);
        float h11 = fmaxf(bv.y + (qq1.x + qq1.y), 0.f);
        u64 hh00 = packf2(h00, h00);
        u64 hh01 = packf2(h01, h01);
        u64 hh10 = packf2(h10, h10);
        u64 hh11 = packf2(h11, h11);

        // ---- scatters: runs of 8 sharing the same hh ----
        a0[0] = fma2(vA0.x, hh00, a0[0]); a0[1] = fma2(vA0.y, hh00, a0[1]);
        a0[2] = fma2(vB0.x, hh00, a0[2]); a0[3] = fma2(vB0.y, hh00, a0[3]);
        a0[4] = fma2(vC0.x, hh00, a0[4]); a0[5] = fma2(vC0.y, hh00, a0[5]);
        a0[6] = fma2(vD0.x, hh00, a0[6]); a0[7] = fma2(vD0.y, hh00, a0[7]);

        a1[0] = fma2(vA0.x, hh01, a1[0]); a1[1] = fma2(vA0.y, hh01, a1[1]);
        a1[2] = fma2(vB0.x, hh01, a1[2]); a1[3] = fma2(vB0.y, hh01, a1[3]);
        a1[4] = fma2(vC0.x, hh01, a1[4]); a1[5] = fma2(vC0.y, hh01, a1[5]);
        a1[6] = fma2(vD0.x, hh01, a1[6]); a1[7] = fma2(vD0.y, hh01, a1[7]);

        a0[0] = fma2(vA1.x, hh10, a0[0]); a0[1] = fma2(vA1.y, hh10, a0[1]);
        a0[2] = fma2(vB1.x, hh10, a0[2]); a0[3] = fma2(vB1.y, hh10, a0[3]);
        a0[4] = fma2(vC1.x, hh10, a0[4]); a0[5] = fma2(vC1.y, hh10, a0[5]);
        a0[6] = fma2(vD1.x, hh10, a0[6]); a0[7] = fma2(vD1.y, hh10, a0[7]);

        a1[0] = fma2(vA1.x, hh11, a1[0]); a1[1] = fma2(vA1.y, hh11, a1[1]);
        a1[2] = fma2(vB1.x, hh11, a1[2]); a1[3] = fma2(vB1.y, hh11, a1[3]);
        a1[4] = fma2(vC1.x, hh11, a1[4]); a1[5] = fma2(vC1.y, hh11, a1[5]);
        a1[6] = fma2(vD1.x, hh11, a1[6]); a1[7] = fma2(vD1.y, hh11, a1[7]);
    }

    // Exchange with partner thread; coupling. Log-det via packed accumulators.
#pragma unroll
    for (int q = 0; q < 8; q++) {
        u64 o0 = __shfl_xor_sync(0xffffffffu, a0[q], 1);
        u64 o1 = __shfl_xor_sync(0xffffffffu, a1[q], 1);
        u64 sv0 = net ? o0 : a0[q];
        u64 tv0 = net ? a0[q] : o0;
        u64 sv1 = net ? o1 : a1[q];
        u64 tv1 = net ? a1[q] : o1;
        lsum0 = add2(lsum0, sv0);
        lsum1 = add2(lsum1, sv1);
        float2 s0 = unpackf2(sv0), t0 = unpackf2(tv0);
        float2 s1 = unpackf2(sv1), t1 = unpackf2(tv1);
        int d0 = 4 * q + 1 - P;
        int d1 = 4 * q + 3 - P;
        z0[d0] = (z0[d0] - t0.x) * __expf(-s0.x);
        z0[d1] = (z0[d1] - t0.y) * __expf(-s0.y);
        z1[d0] = (z1[d0] - t1.x) * __expf(-s1.x);
        z1[d1] = (z1[d1] - t1.y) * __expf(-s1.y);
    }
}

__device__ __forceinline__ void prefetch_layer(float* dst, const float* src) {
    int t = threadIdx.x;
#pragma unroll
    for (int q = 0; q < 9; q++) {
        int idx = t + q * 128;          // 16B units; total PK/4 = 1088
        if (idx < PK / 4) cp_async16(dst + idx * 4, src + idx * 4);
    }
}

__global__ void __launch_bounds__(128, 1)
flow_kernel(const float* __restrict__ nodes, const float* __restrict__ loc,
            const float* __restrict__ lsc) {
    __shared__ __align__(16) float sw[2][PK];
    const int c    = blockIdx.y;
    const int net  = threadIdx.x & 1;                 // 0 = s-net, 1 = t-net
    const int pair = threadIdx.x >> 1;                // 0..63
    const int n0   = blockIdx.x * 128 + pair;
    const int n1   = n0 + 64;
    const int wo   = net * NETOFF;

    float z0[32], z1[32];
#pragma unroll
    for (int q = 0; q < 8; q++) {
        float4 v0 = *reinterpret_cast<const float4*>(nodes + n0 * 32 + q * 4);
        z0[q * 4] = v0.x; z0[q * 4 + 1] = v0.y; z0[q * 4 + 2] = v0.z; z0[q * 4 + 3] = v0.w;
        float4 v1 = *reinterpret_cast<const float4*>(nodes + n1 * 32 + q * 4);
        z1[q * 4] = v1.x; z1[q * 4 + 1] = v1.y; z1[q * 4 + 2] = v1.z; z1[q * 4 + 3] = v1.w;
    }
    float ld0 = 0.f, ld1 = 0.f;
    u64 lsum0 = 0ull, lsum1 = 0ull;   // packed sum of s-values (subtracted at end)

    const float* gp = g_packed + (size_t)c * (KK * PK);
    prefetch_layer(sw[1], gp + 63 * PK);   // layer 63 -> buf (63&1)=1
    cp_commit();

    for (int it = 0; it < 64; it++) {
        const int k = 63 - it;
        const int b = k & 1;
        cp_wait0();
        __syncthreads();
        if (it < 63) prefetch_layer(sw[b ^ 1], gp + (k - 1) * PK);
        cp_commit();
        if (b) layer_step<1>(sw[b], wo, net, z0, z1, ld0, ld1, lsum0, lsum1);
        else   layer_step<0>(sw[b], wo, net, z0, z1, ld0, ld1, lsum0, lsum1);
        // next iteration's top __syncthreads guards buffer reuse
    }

    // fold packed s-sums into scalar log-dets
    {
        float2 t0 = unpackf2(lsum0);
        float2 t1 = unpackf2(lsum1);
        ld0 -= t0.x + t0.y;
        ld1 -= t1.x + t1.y;
    }

    // DiagGaussian log prob + exp + block L1-sum
    float lq0 = ld0 - 29.40603306254953f;    // 0.5 * D * log(2*pi)
    float lq1 = ld1 - 29.40603306254953f;
    const float* lc = loc + c * 32;
    const float* ls = lsc + c * 32;
#pragma unroll
    for (int d = 0; d < 32; d++) {
        float l = ls[d];
        float e = __expf(-l);
        float u0 = (z0[d] - lc[d]) * e;
        float u1 = (z1[d] - lc[d]) * e;
        lq0 -= l + 0.5f * u0 * u0;
        lq1 -= l + 0.5f * u1 * u1;
    }
    float e0 = expf(lq0);
    float e1 = expf(lq1);
    if (net == 0) {
        g_E[n0 * CC + c] = e0;
        g_E[n1 * CC + c] = e1;
    }
    __syncthreads();                       // done with sw weights
    float* red = sw[0];
    red[threadIdx.x] = (net == 0) ? (e0 + e1) : 0.f;
    __syncthreads();
    for (int w = 64; w > 0; w >>= 1) {
        if (threadIdx.x < w) red[threadIdx.x] += red[threadIdx.x + w];
        __syncthreads();
    }
    if (threadIdx.x == 0) atomicAdd(&g_den[c], red[0]);
}

// ---------------------------------------------------------------------------
// Kernel 5: G = Bm normalized (clamped), A = S-weighted; S computed in-kernel
// ---------------------------------------------------------------------------
__global__ void ga_kernel(const float* __restrict__ S_unc) {
    __shared__ float sS[64];
    __shared__ float sden[8];
    __shared__ float stot;
    if (threadIdx.x < 64) sS[threadIdx.x] = expf(S_unc[threadIdx.x]);
    if (threadIdx.x >= 64 && threadIdx.x < 72)
        sden[threadIdx.x - 64] = fmaxf(g_den[threadIdx.x - 64], 1e-12f);
    __syncthreads();
    if (threadIdx.x == 0) {
        float s = 0.f;
        for (int i = 0; i < 64; i++) s += sS[i];
        stot = 1.f / s;
    }
    __syncthreads();
    float stot_l = stot;
    int j = blockIdx.x * 256 + threadIdx.x;
    float g[8];
#pragma unroll
    for (int c = 0; c < 8; c++) g[c] = g_E[j * CC + c] / sden[c];
#pragma unroll
    for (int c = 0; c < 8; c++) g_G[j * CC + c] = g[c];
#pragma unroll
    for (int c = 0; c < 8; c++) {
        float a = 0.f;
#pragma unroll
        for (int c2 = 0; c2 < 8; c2++) a = fmaf(sS[c * 8 + c2] * stot_l, g[c2], a);
        g_A[j * CC + c] = a;
    }
}

// ---------------------------------------------------------------------------
// Kernel 6: out[i][j] = sum_c G[i][c] * A[j][c]   (rank-8, 64x64 tiles)
// ---------------------------------------------------------------------------
__global__ void __launch_bounds__(256) outer_kernel(float* __restrict__ out) {
    __shared__ float Gs[64][8];
    __shared__ float As[64][8];
    int i0 = blockIdx.y * 64, j0 = blockIdx.x * 64;
    int t = threadIdx.x;
    for (int q = t; q < 512; q += 256) {
        ((float*)Gs)[q] = g_G[i0 * 8 + q];
        ((float*)As)[q] = g_A[j0 * 8 + q];
    }
    __syncthreads();
    int tx = t & 15, ty = t >> 4;
    float gr[4][8], ar[4][8];
#pragma unroll
    for (int r = 0; r < 4; r++)
#pragma unroll
        for (int c = 0; c < 8; c++) {
            gr[r][c] = Gs[ty * 4 + r][c];
            ar[r][c] = As[tx * 4 + r][c];
        }
#pragma unroll
    for (int r = 0; r < 4; r++) {
        float4 o;
        float acc[4] = {0.f, 0.f, 0.f, 0.f};
#pragma unroll
        for (int c = 0; c < 8; c++) {
            acc[0] = fmaf(gr[r][c], ar[0][c], acc[0]);
            acc[1] = fmaf(gr[r][c], ar[1][c], acc[1]);
            acc[2] = fmaf(gr[r][c], ar[2][c], acc[2]);
            acc[3] = fmaf(gr[r][c], ar[3][c], acc[3]);
        }
        o.x = acc[0]; o.y = acc[1]; o.z = acc[2]; o.w = acc[3];
        *reinterpret_cast<float4*>(out + (size_t)(i0 + ty * 4 + r) * NN + j0 + tx * 4) = o;
    }
}

// ---------------------------------------------------------------------------
extern "C" void kernel_launch(void* const* d_in, const int* in_sizes, int n_in,
                              void* d_out, int out_size) {
    const float* nodes = (const float*)d_in[0];
    const float* sW1   = (const float*)d_in[1];
    const float* sb1   = (const float*)d_in[2];
    const float* sW2   = (const float*)d_in[3];
    const float* sb2   = (const float*)d_in[4];
    const float* tW1   = (const float*)d_in[5];
    const float* tb1   = (const float*)d_in[6];
    const float* tW2   = (const float*)d_in[7];
    const float* tb2   = (const float*)d_in[8];
    const float* ans   = (const float*)d_in[9];
    const float* ant   = (const float*)d_in[10];
    const float* loc   = (const float*)d_in[11];
    const float* lsc   = (const float*)d_in[12];
    const float* Sunc  = (const float*)d_in[13];
    float* out = (float*)d_out;

    pack_kernel<<<CC * KK, 256>>>(sW1, sb1, sW2, sb2, tW1, tb1, tW2, tb2, ans, ant);
    // Keep flow_kernel in the ncu-profiled (4th) launch slot.
    nop_kernel<<<1, 32>>>();
    nop_kernel<<<1, 32>>>();
    flow_kernel<<<dim3(NN / 128, CC), 128>>>(nodes, loc, lsc);
    ga_kernel<<<NN / 256, 256>>>(Sunc);
    outer_kernel<<<dim3(NN / 64, NN / 64), 256>>>(out);
}